// round 1
// baseline (speedup 1.0000x reference)
#include <cuda_runtime.h>
#include <cstdint>

// ---------------- problem constants ----------------
#define NB      256     // bases
#define KD      768     // patch dim (3*16*16)
#define NIMG    64
#define NROW    27      // patch rows (= cols) per image
#define NPATIMG 729     // 27*27
#define ITERS   50

typedef unsigned long long u64;

// ---------------- device scratch (static: allocation-free) ----------------
__device__ float        g_gram[NB * NB];                 // D D^T - I
__device__ float        g_colsum[NB];                    // row sums of D
__device__ float        g_b[(size_t)NIMG * NPATIMG * NB];// feedforward drive (47.8 MB)
__device__ unsigned int g_maxbits[NIMG * NB];            // monotone-encoded running max

// ---------------- helpers ----------------
__device__ __forceinline__ void fma2(u64 &acc, u64 a, u64 b) {
    asm("fma.rn.f32x2 %0, %1, %2, %0;" : "+l"(acc) : "l"(a), "l"(b));
}
__device__ __forceinline__ float hsum2(u64 v) {
    unsigned int lo, hi;
    asm("mov.b64 {%0,%1}, %2;" : "=r"(lo), "=r"(hi) : "l"(v));
    return __uint_as_float(lo) + __uint_as_float(hi);
}
__device__ __forceinline__ float softshrink(float x) {
    return copysignf(fmaxf(fabsf(x) - 0.5f, 0.0f), x);
}
// monotone float->uint encoding so unsigned atomicMax == float max
__device__ __forceinline__ unsigned int enc_f(float x) {
    unsigned int b = __float_as_uint(x);
    return (b & 0x80000000u) ? ~b : (b | 0x80000000u);
}

// ---------------- K0: init running max ----------------
__global__ void init_kernel() {
    g_maxbits[blockIdx.x * NB + threadIdx.x] = 0u;  // key 0 < enc of any real float
}

// ---------------- K1: gram = D D^T - I, colsum ----------------
__global__ void __launch_bounds__(256) gram_kernel(const float* __restrict__ D) {
    __shared__ float di[KD];
    __shared__ float red[256];
    const int i = blockIdx.x;
    const int t = threadIdx.x;

    // stage row i
    const float4* Di4 = (const float4*)(D + (size_t)i * KD);
    for (int q = t; q < KD / 4; q += 256) ((float4*)di)[q] = Di4[q];
    __syncthreads();

    // dot(row i, row t)
    const float4* Dj4 = (const float4*)(D + (size_t)t * KD);
    float acc = 0.f;
    #pragma unroll 4
    for (int q = 0; q < KD / 4; q++) {
        float4 v = __ldg(&Dj4[q]);
        acc += v.x * di[4*q] + v.y * di[4*q+1] + v.z * di[4*q+2] + v.w * di[4*q+3];
    }
    g_gram[i * NB + t] = acc - ((i == t) ? 1.0f : 0.0f);

    // colsum of row i (block reduce)
    red[t] = di[t] + di[t + 256] + di[t + 512];
    __syncthreads();
    for (int o = 128; o > 0; o >>= 1) {
        if (t < o) red[t] += red[t + o];
        __syncthreads();
    }
    if (t == 0) g_colsum[i] = red[0];
}

// ---------------- K2: patch strip -> b = std_fold(raw @ D^T) ----------------
// one CTA per (image, patch-row). smem: strip[3*16*224] + dt2[32][256] f32x2 D tile.
#define K2_STRIP_F   (3 * 16 * 224)              // 10752 floats
#define K2_DT2_OFF   43264                       // byte offset (strip 43008 + stats, aligned)
#define K2_SMEM      (K2_DT2_OFF + 32 * 256 * 8) // 108800 B

__global__ void __launch_bounds__(256, 1) b_kernel(const float* __restrict__ img,
                                                   const float* __restrict__ D) {
    extern __shared__ char smraw[];
    float* strip  = (float*)smraw;                       // [48 rows][224]
    float* mean_s = strip + K2_STRIP_F;                  // [28]
    float* inv_s  = mean_s + 28;                         // [28]
    u64*   dt2    = (u64*)(smraw + K2_DT2_OFF);          // [32 dpairs][256 n]

    const int blk = blockIdx.x;
    const int im  = blk / NROW;
    const int py  = blk - im * NROW;
    const int t   = threadIdx.x;
    const int pt  = t >> 6;     // 0..3  (patch group)
    const int nt  = t & 63;     // 0..63 (basis lane)

    // ---- load strip: rows y in [8*py, 8*py+16) for all 3 channels ----
    const float* ibase = img + (size_t)im * 3 * 224 * 224 + (size_t)(py * 8) * 224;
    for (int e = t; e < K2_STRIP_F; e += 256) {
        int c   = e / 3584;             // 16*224
        int rem = e - c * 3584;         // ph*224 + x
        strip[e] = ibase[(size_t)c * 224 * 224 + rem];
    }
    __syncthreads();

    // ---- per-patch mean / unbiased std (8 lanes per patch, all lanes active) ----
    {
        int p  = t >> 3; if (p > 26) p = 26;   // clamp: lanes 216..255 redundant
        int l8 = t & 7;
        float sm = 0.f, sq = 0.f;
        int xoff = p * 8;
        for (int d = l8; d < KD; d += 8) {
            int rowi = d >> 4;          // c*16+ph
            int pw   = d & 15;
            float v = strip[rowi * 224 + xoff + pw];
            sm += v; sq += v * v;
        }
        #pragma unroll
        for (int o = 4; o > 0; o >>= 1) {
            sm += __shfl_down_sync(0xffffffffu, sm, o);
            sq += __shfl_down_sync(0xffffffffu, sq, o);
        }
        if (l8 == 0 && (t >> 3) < 27) {
            float m   = sm * (1.0f / 768.0f);
            float var = fmaxf(sq - sm * sm * (1.0f / 768.0f), 0.0f) * (1.0f / 767.0f);
            mean_s[p] = m;
            inv_s[p]  = 1.0f / (sqrtf(var) + 1e-8f);
        }
    }

    // ---- GEMM: raw[p][n] = sum_d strip(p,d) * D[n][d], f32x2 over d-pairs ----
    u64 acc[4][7];
    #pragma unroll
    for (int i = 0; i < 4; i++)
        #pragma unroll
        for (int k = 0; k < 7; k++) acc[i][k] = 0ull;

    const u64* Dg = (const u64*)D;   // row = 384 u64
    #pragma unroll 1
    for (int d0 = 0; d0 < KD; d0 += 64) {
        __syncthreads();
        #pragma unroll
        for (int r = 0; r < 32; r++) {
            int n = r * 8 + (t >> 5);
            dt2[(size_t)(t & 31) * NB + n] = __ldg(&Dg[(size_t)n * 384 + (d0 >> 1) + (t & 31)]);
        }
        __syncthreads();

        #pragma unroll 4
        for (int q = 0; q < 32; q++) {
            int d    = d0 + 2 * q;
            int rowi = d >> 4;
            int pw   = d & 15;
            const float* srow = strip + rowi * 224 + pw;
            u64 av[7];
            #pragma unroll
            for (int k = 0; k < 7; k++) {
                int p  = pt * 7 + k;
                int px = (p > 26) ? 26 : p;          // dummy patch 27 clamps
                av[k] = *(const u64*)(srow + px * 8);
            }
            #pragma unroll
            for (int i = 0; i < 4; i++) {
                u64 g = dt2[(size_t)q * NB + nt + 64 * i];
                #pragma unroll
                for (int k = 0; k < 7; k++) fma2(acc[i][k], av[k], g);
            }
        }
    }

    // ---- epilogue: fold standardization, write b ----
    float* bout = g_b + (size_t)(im * NPATIMG + py * NROW) * NB;
    #pragma unroll
    for (int i = 0; i < 4; i++) {
        int n = nt + 64 * i;
        float cs = __ldg(&g_colsum[n]);
        #pragma unroll
        for (int k = 0; k < 7; k++) {
            int p = pt * 7 + k;
            if (p < 27) {
                float raw = hsum2(acc[i][k]);
                bout[(size_t)p * NB + n] = (raw - mean_s[p] * cs) * inv_s[p];
            }
        }
    }
}

// ---------------- K3: fused LCA (all 50 iterations per CTA) ----------------
// one CTA per (image, patch-row) = 27 patches (+1 dummy). Thread: 4 bases x 7 patches.
#define K3_AS_F   (28 * NB)                  // a in smem, [28][256]
#define K3_GS_OFF (K3_AS_F * 4)              // 28672 B
#define K3_SMEM   (K3_GS_OFF + 256 * 33 * 8) // 96256 B (gram chunk [256 n][33 jpairs])

__global__ void __launch_bounds__(256, 1) lca_kernel() {
    extern __shared__ char smraw[];
    float* a_s = (float*)smraw;                 // [p 0..27][n 0..255]
    u64*   gs2 = (u64*)(smraw + K3_GS_OFF);     // [n][33] padded j-pairs

    const int blk = blockIdx.x;
    const int im  = blk / NROW;
    const int py  = blk - im * NROW;
    const int t   = threadIdx.x;
    const int pt  = t >> 6;
    const int nt  = t & 63;

    float u[4][7], brg[4][7];
    const float* bbase = g_b + (size_t)(im * NPATIMG + py * NROW) * NB;
    #pragma unroll
    for (int i = 0; i < 4; i++)
        #pragma unroll
        for (int k = 0; k < 7; k++) {
            int p = pt * 7 + k;
            brg[i][k] = (p < 27) ? bbase[(size_t)p * NB + nt + 64 * i] : 0.0f;
            u[i][k] = 0.0f;
        }

    const u64* G2 = (const u64*)g_gram;   // row = 128 u64

    for (int it = 0; it < ITERS; it++) {
        __syncthreads();   // prev-iter a_s readers done
        #pragma unroll
        for (int i = 0; i < 4; i++)
            #pragma unroll
            for (int k = 0; k < 7; k++) {
                int p = pt * 7 + k;        // includes dummy row 27 (stays zero)
                a_s[p * NB + nt + 64 * i] = softshrink(u[i][k]);
            }

        u64 acc[4][7];
        #pragma unroll
        for (int i = 0; i < 4; i++)
            #pragma unroll
            for (int k = 0; k < 7; k++) acc[i][k] = 0ull;

        #pragma unroll 1
        for (int j0 = 0; j0 < NB; j0 += 64) {
            __syncthreads();   // prev chunk consumers done
            #pragma unroll
            for (int r = 0; r < 32; r++) {
                int n = r * 8 + (t >> 5);
                gs2[n * 33 + (t & 31)] = __ldg(&G2[(size_t)n * 128 + (j0 >> 1) + (t & 31)]);
            }
            __syncthreads();

            #pragma unroll 4
            for (int q = 0; q < 32; q++) {
                u64 av[7];
                #pragma unroll
                for (int k = 0; k < 7; k++) {
                    int p = pt * 7 + k;
                    av[k] = *(const u64*)(a_s + p * NB + j0 + 2 * q);
                }
                #pragma unroll
                for (int i = 0; i < 4; i++) {
                    u64 g = gs2[(nt + 64 * i) * 33 + q];
                    #pragma unroll
                    for (int k = 0; k < 7; k++) fma2(acc[i][k], av[k], g);
                }
            }
        }

        // u += 0.01 * (b - u - a@gram)
        #pragma unroll
        for (int i = 0; i < 4; i++)
            #pragma unroll
            for (int k = 0; k < 7; k++) {
                float s = hsum2(acc[i][k]);
                u[i][k] += 0.01f * (brg[i][k] - u[i][k] - s);
            }
    }

    // epilogue: codes = softshrink(u); running max per (image, basis)
    #pragma unroll
    for (int i = 0; i < 4; i++) {
        float cm = -__int_as_float(0x7f800000);  // -inf
        #pragma unroll
        for (int k = 0; k < 7; k++) {
            int p = pt * 7 + k;
            if (p < 27) cm = fmaxf(cm, softshrink(u[i][k]));
        }
        atomicMax(&g_maxbits[im * NB + nt + 64 * i], enc_f(cm));
    }
}

// ---------------- K4: decode running max to output ----------------
__global__ void finalize_kernel(float* __restrict__ out) {
    int idx = blockIdx.x * NB + threadIdx.x;
    unsigned int k = g_maxbits[idx];
    out[idx] = (k & 0x80000000u) ? __uint_as_float(k & 0x7fffffffu)
                                 : __uint_as_float(~k);
}

// ---------------- launch ----------------
extern "C" void kernel_launch(void* const* d_in, const int* in_sizes, int n_in,
                              void* d_out, int out_size) {
    const float* image = (const float*)d_in[0];
    const float* dict  = (const float*)d_in[1];
    float* out = (float*)d_out;

    cudaFuncSetAttribute(b_kernel,   cudaFuncAttributeMaxDynamicSharedMemorySize, K2_SMEM);
    cudaFuncSetAttribute(lca_kernel, cudaFuncAttributeMaxDynamicSharedMemorySize, K3_SMEM);

    init_kernel<<<NIMG, NB>>>();
    gram_kernel<<<NB, 256>>>(dict);
    b_kernel<<<NIMG * NROW, 256, K2_SMEM>>>(image, dict);
    lca_kernel<<<NIMG * NROW, 256, K3_SMEM>>>();
    finalize_kernel<<<NIMG, NB>>>(out);
}